// round 17
// baseline (speedup 1.0000x reference)
#include <cuda_runtime.h>

#define KSEL     5000
#define CAP      65536
#define SMEMCAP  8192
#define FT       1024
#define NPT_CAND 8           // SMEMCAP / FT
#define BUFCAP   2048
#define XGUESS   3.65f
#define NHIST    4096
#define NB       4096
#define EQB      2048
#define DST_N    5120
#define FIN_SMEM (DST_N*8 + NB*4 + EQB*8)   // 73728 bytes

// ---------------- scratch (static device globals; zero-initialized) ---------
__device__ unsigned long long g_c64[CAP];  // candidates: (key<<32) | idx
__device__ unsigned g_hist[NHIST];         // coarse histogram of (key-UB)>>13
__device__ unsigned g_total;
__device__ unsigned g_ovf;

__device__ __forceinline__ unsigned f2u(float f) {
    unsigned b = __float_as_uint(f);
    return (b & 0x80000000u) ? ~b : (b | 0x80000000u);
}
__device__ __forceinline__ float u2f(unsigned u) {
    return __uint_as_float((u & 0x80000000u) ? (u & 0x7fffffffu) : ~u);
}

// ---------------- K1: streaming compaction + coarse histogram (proven) ------
__global__ void __launch_bounds__(512) k_compact(const float* __restrict__ x, int n) {
    __shared__ unsigned s_cnt, s_base;
    __shared__ unsigned skey[BUFCAP];
    __shared__ unsigned sidx[BUFCAP];
    if (threadIdx.x == 0) s_cnt = 0;
    __syncthreads();

    const int n4 = n >> 2;
    const float4* __restrict__ x4 = (const float4*)x;
    const int stride = gridDim.x * blockDim.x;
    int i = blockIdx.x * blockDim.x + threadIdx.x;

    #define PROC4(v, base_) do {                                                  \
        float mx = fmaxf(fmaxf((v).x, (v).y), fmaxf((v).z, (v).w));               \
        unsigned am = __activemask();                                             \
        if (__ballot_sync(am, mx > XGUESS)) {                                     \
            if ((v).x > XGUESS) { unsigned p = atomicAdd(&s_cnt, 1u); if (p < BUFCAP) { skey[p] = f2u((v).x); sidx[p] = (base_) + 0; } } \
            if ((v).y > XGUESS) { unsigned p = atomicAdd(&s_cnt, 1u); if (p < BUFCAP) { skey[p] = f2u((v).y); sidx[p] = (base_) + 1; } } \
            if ((v).z > XGUESS) { unsigned p = atomicAdd(&s_cnt, 1u); if (p < BUFCAP) { skey[p] = f2u((v).z); sidx[p] = (base_) + 2; } } \
            if ((v).w > XGUESS) { unsigned p = atomicAdd(&s_cnt, 1u); if (p < BUFCAP) { skey[p] = f2u((v).w); sidx[p] = (base_) + 3; } } \
        }                                                                         \
    } while (0)

    for (; i + 3 * stride < n4; i += 4 * stride) {
        float4 a = __ldcs(x4 + i);
        float4 b = __ldcs(x4 + i + stride);
        float4 c = __ldcs(x4 + i + 2 * stride);
        float4 d = __ldcs(x4 + i + 3 * stride);
        PROC4(a, (unsigned)i << 2);
        PROC4(b, (unsigned)(i + stride) << 2);
        PROC4(c, (unsigned)(i + 2 * stride) << 2);
        PROC4(d, (unsigned)(i + 3 * stride) << 2);
    }
    for (; i < n4; i += stride) {
        float4 a = __ldcs(x4 + i);
        PROC4(a, (unsigned)i << 2);
    }
    if (blockIdx.x == 0) {       // scalar tail (n not divisible by 4)
        for (int t = (n4 << 2) + threadIdx.x; t < n; t += blockDim.x) {
            float v = x[t];
            if (v > XGUESS) { unsigned p = atomicAdd(&s_cnt, 1u); if (p < BUFCAP) { skey[p] = f2u(v); sidx[p] = (unsigned)t; } }
        }
    }
    __syncthreads();

    unsigned cnt = s_cnt;
    if (cnt > BUFCAP) { if (threadIdx.x == 0) g_ovf = 1u; cnt = BUFCAP; }
    if (threadIdx.x == 0) s_base = atomicAdd(&g_total, cnt);
    __syncthreads();
    const unsigned UB = f2u(XGUESS);
    unsigned base = s_base;
    for (unsigned j = threadIdx.x; j < cnt; j += blockDim.x) {
        unsigned q = base + j;
        unsigned key = skey[j];
        if (q < CAP) g_c64[q] = ((unsigned long long)key << 32)
                              | (unsigned long long)sidx[j];
        unsigned b = (key - UB) >> 13; if (b > NHIST - 1u) b = NHIST - 1u;
        atomicAdd(&g_hist[b], 1u);
    }
    cudaTriggerProgrammaticLaunchCompletion();
}

// ---- vectorized hierarchical inclusive SUFFIX scan, 1024 threads -----------
template <int NBINS>
__device__ __forceinline__ void suffix_scan_block(unsigned* b, unsigned* wsum) {
    constexpr int NPT = NBINS / FT;
    constexpr int NV = NPT / 4;
    const unsigned tid = threadIdx.x;
    const unsigned lane = tid & 31u, wid = tid >> 5;
    uint4* b4 = (uint4*)b;
    unsigned v[NPT]; unsigned tsum = 0;
    #pragma unroll
    for (int q = 0; q < NV; q++) {
        uint4 t4 = b4[tid * NV + q];
        v[q*4+0]=t4.x; v[q*4+1]=t4.y; v[q*4+2]=t4.z; v[q*4+3]=t4.w;
    }
    #pragma unroll
    for (int k = 0; k < NPT; k++) tsum += v[k];
    unsigned inc = tsum;
    #pragma unroll
    for (int d = 1; d < 32; d <<= 1) {
        unsigned o = __shfl_down_sync(0xffffffffu, inc, d);
        if (lane + d < 32) inc += o;
    }
    if (lane == 0) wsum[wid] = inc;
    __syncthreads();
    if (wid == 0) {
        unsigned w = wsum[lane];
        unsigned wi = w;
        #pragma unroll
        for (int d = 1; d < 32; d <<= 1) {
            unsigned o = __shfl_down_sync(0xffffffffu, wi, d);
            if (lane + d < 32) wi += o;
        }
        wsum[lane] = wi - w;                 // sum of warps after this warp
    }
    __syncthreads();
    unsigned acc = wsum[wid] + (inc - tsum);
    #pragma unroll
    for (int k = NPT - 1; k >= 0; k--) { acc += v[k]; v[k] = acc; }
    #pragma unroll
    for (int q = 0; q < NV; q++)
        b4[tid * NV + q] = make_uint4(v[q*4+0], v[q*4+1], v[q*4+2], v[q*4+3]);
    __syncthreads();
}

// ---- vectorized hierarchical EXCLUSIVE scan over NB bins, 1024 threads -----
__device__ __forceinline__ void excl_scan_nb(unsigned* b, unsigned* wsum) {
    constexpr int NPT = NB / FT;        // 4
    const unsigned tid = threadIdx.x;
    const unsigned lane = tid & 31u, wid = tid >> 5;
    uint4* b4 = (uint4*)b;
    uint4 t4 = b4[tid];
    unsigned v[4] = { t4.x, t4.y, t4.z, t4.w };
    unsigned pre[4]; unsigned tsum = 0;
    #pragma unroll
    for (int k = 0; k < NPT; k++) { pre[k] = tsum; tsum += v[k]; }
    unsigned inc = tsum;
    #pragma unroll
    for (int d = 1; d < 32; d <<= 1) {
        unsigned o = __shfl_up_sync(0xffffffffu, inc, d);
        if (lane >= (unsigned)d) inc += o;
    }
    if (lane == 31) wsum[wid] = inc;
    __syncthreads();
    if (wid == 0) {
        unsigned w = wsum[lane];
        unsigned wi = w;
        #pragma unroll
        for (int d = 1; d < 32; d <<= 1) {
            unsigned o = __shfl_up_sync(0xffffffffu, wi, d);
            if (lane >= (unsigned)d) wi += o;
        }
        wsum[lane] = wi - w;
    }
    __syncthreads();
    unsigned base = wsum[wid] + (inc - tsum);
    b4[tid] = make_uint4(base+pre[0], base+pre[1], base+pre[2], base+pre[3]);
    __syncthreads();
}

// ---------------- K2: everything after the stream, one block (PDL) ----------
__global__ void __launch_bounds__(FT, 1) k_final(const float* __restrict__ x, int n,
                                                 float* __restrict__ out) {
    extern __shared__ unsigned long long sm[];
    unsigned long long* dst = sm;                   // DST_N u64 (idx<<32|key)
    unsigned* bcnt = (unsigned*)(dst + DST_N);      // NB u32 (buckets)
    unsigned long long* eqb = (unsigned long long*)(bcnt + NB);  // EQB u64
    unsigned* cbin = (unsigned*)eqb;                // NHIST u32 (coarse; reused)
    __shared__ unsigned sh_d, sh_ab, s_cnt, wsum[32];
    const unsigned tid = threadIdx.x;
    const unsigned UB = f2u(XGUESS);

    // ---- independent preamble: zero bucket array while stream still runs
    ((uint4*)bcnt)[tid] = make_uint4(0, 0, 0, 0);
    cudaGridDependencySynchronize();   // wait for k_compact's results

    unsigned tot = g_total;
    bool need_fb = !((g_ovf == 0u) && tot >= (unsigned)KSEL && tot <= (unsigned)SMEMCAP
                     && (g_hist[NHIST - 1] < (unsigned)KSEL));
    unsigned T = tot > (unsigned)SMEMCAP ? (unsigned)SMEMCAP : tot;

    // register-resident candidates (one u64 LDG burst)
    unsigned uk[NPT_CAND], ui[NPT_CAND];
    #pragma unroll
    for (int k = 0; k < NPT_CAND; k++) {
        unsigned j = tid + (unsigned)k * FT;
        unsigned long long c = (j < T) ? g_c64[j] : 0ull;   // key 0 never kept
        uk[k] = (unsigned)(c >> 32);
        ui[k] = (unsigned)c;
    }

    unsigned uT = 0, cut = 0xffffffffu;
    if (!need_fb) {
        // ---- coarse suffix scan over g_hist (4096 bins, in cbin/eqb region)
        for (unsigned t = tid; t < NHIST; t += FT) cbin[t] = g_hist[t];
        __syncthreads();
        suffix_scan_block<NHIST>(cbin, wsum);
        for (unsigned t = tid; t < NHIST; t += FT) {
            unsigned nxt = (t + 1 < NHIST) ? cbin[t + 1] : 0;
            if (cbin[t] >= (unsigned)KSEL && nxt < (unsigned)KSEL) { sh_d = t; sh_ab = nxt; }
        }
        __syncthreads();
        const unsigned d = sh_d;
        const unsigned need2 = (unsigned)KSEL - sh_ab;   // >= 1
        const unsigned cnt_d = cbin[d] - sh_ab;
        __syncthreads();                                 // cbin done; eqb reusable

        if (cnt_d > (unsigned)EQB) {
            need_fb = true;
        } else {
            // ---- gather bin-d entries: e = (key<<32) | ~idx (warp-aggregated)
            if (tid == 0) s_cnt = 0;
            __syncthreads();
            #pragma unroll
            for (int k = 0; k < NPT_CAND; k++) {
                bool pred = (((uk[k] - UB) >> 13) == d) && (uk[k] != 0u);
                unsigned mask = __ballot_sync(0xffffffffu, pred);
                if (mask) {
                    unsigned lane = tid & 31u;
                    unsigned leader = (unsigned)(__ffs(mask) - 1);
                    unsigned wbase = 0;
                    if (lane == leader) wbase = atomicAdd(&s_cnt, (unsigned)__popc(mask));
                    wbase = __shfl_sync(0xffffffffu, wbase, leader);
                    if (pred) {
                        unsigned pos = wbase + (unsigned)__popc(mask & ((1u << lane) - 1u));
                        if (pos < (unsigned)EQB)
                            eqb[pos] = ((unsigned long long)uk[k] << 32)
                                     | (unsigned long long)(~ui[k]);
                    }
                }
            }
            __syncthreads();
            unsigned m = s_cnt;                          // == cnt_d <= EQB
            unsigned np2 = 2; while (np2 < m) np2 <<= 1;
            for (unsigned t = tid; t < np2; t += FT)
                if (t >= m) eqb[t] = 0ull;               // pad sorts last (desc)
            __syncthreads();
            if (np2 <= 256u) {
                // warp 0 sorts alone: no block barriers in the phase loop
                if (tid < 32u) {
                    for (unsigned k2 = 2; k2 <= np2; k2 <<= 1) {
                        for (unsigned j2 = k2 >> 1; j2 > 0; j2 >>= 1) {
                            for (unsigned t = tid; t < np2 / 2; t += 32u) {
                                unsigned i2 = ((t & ~(j2 - 1)) << 1) | (t & (j2 - 1));
                                unsigned p2 = i2 | j2;
                                unsigned long long a = eqb[i2], b = eqb[p2];
                                bool up = ((i2 & k2) == 0);
                                if ((a < b) == up) { eqb[i2] = b; eqb[p2] = a; }
                            }
                            __syncwarp();
                        }
                    }
                }
                __syncthreads();
            } else {
                for (unsigned k2 = 2; k2 <= np2; k2 <<= 1) { // block bitonic DESC
                    for (unsigned j2 = k2 >> 1; j2 > 0; j2 >>= 1) {
                        for (unsigned t = tid; t < np2 / 2; t += FT) {
                            unsigned i2 = ((t & ~(j2 - 1)) << 1) | (t & (j2 - 1));
                            unsigned p2 = i2 | j2;
                            unsigned long long a = eqb[i2], b = eqb[p2];
                            bool up = ((i2 & k2) == 0);
                            if ((a < b) == up) { eqb[i2] = b; eqb[p2] = a; }
                        }
                        __syncthreads();
                    }
                }
            }
            unsigned long long e = eqb[need2 - 1];       // exact boundary entry
            uT = (unsigned)(e >> 32);
            cut = ~(unsigned)e;                          // largest kept tie idx
            __syncthreads();
        }
    }

    if (need_fb) {
        // ===== exact full-input fallback (cold; never on sane inputs) ========
        unsigned* bins = bcnt;
        unsigned prefix = 0, prefmask = 0, need = KSEL;
        const int vsh[3] = { 21, 10, 0 };
        const int vwd[3] = { 11, 11, 10 };
        for (int r = 0; r < 3; r++) {
            const int sh = vsh[r];
            const int nb = 1 << vwd[r];
            for (int t = tid; t < nb; t += FT) bins[t] = 0;
            __syncthreads();
            for (int i = tid; i < n; i += FT) {
                unsigned u = f2u(x[i]);
                if ((u & prefmask) == prefix) {
                    unsigned b = (u >> sh) & (unsigned)(nb - 1);
                    unsigned am = __activemask();
                    unsigned peers = __match_any_sync(am, b);
                    if ((tid & 31u) == (unsigned)(__ffs(peers) - 1))
                        atomicAdd(&bins[b], (unsigned)__popc(peers));
                }
            }
            __syncthreads();
            for (int d2 = 1; d2 < nb; d2 <<= 1) {      // suffix Hillis-Steele
                unsigned t0 = tid, t1 = tid + FT;
                unsigned a0 = (t0 < (unsigned)nb && t0 + d2 < (unsigned)nb) ? bins[t0 + d2] : 0;
                unsigned a1 = (t1 < (unsigned)nb && t1 + d2 < (unsigned)nb) ? bins[t1 + d2] : 0;
                __syncthreads();
                if (t0 < (unsigned)nb) bins[t0] += a0;
                if (t1 < (unsigned)nb) bins[t1] += a1;
                __syncthreads();
            }
            for (int t = tid; t < nb; t += FT) {
                unsigned nxt = (t + 1 < nb) ? bins[t + 1] : 0;
                if (bins[t] >= need && nxt < need) sh_d = (unsigned)t;
            }
            __syncthreads();
            unsigned d2 = sh_d;
            unsigned above = (d2 + 1 < (unsigned)nb) ? bins[d2 + 1] : 0;
            __syncthreads();
            need -= above;
            prefix |= d2 << sh;
            prefmask |= ((unsigned)(nb - 1)) << sh;
        }
        const unsigned uTf = prefix;
        const unsigned Rf = need;

        unsigned iprefix = 0, imask = 0, needi = Rf;
        const int ish[3] = { 15, 4, 0 };
        const int iwd[3] = { 11, 11, 4 };
        if (Rf > 0) {
            for (int r = 0; r < 3; r++) {
                const int sh = ish[r];
                const int nb = 1 << iwd[r];
                for (int t = tid; t < nb; t += FT) bins[t] = 0;
                __syncthreads();
                for (int i = tid; i < n; i += FT) {
                    unsigned u = f2u(x[i]);
                    if (u == uTf && (((unsigned)i & imask) == iprefix))
                        atomicAdd(&bins[((unsigned)i >> sh) & (unsigned)(nb - 1)], 1u);
                }
                __syncthreads();
                for (int d2 = 1; d2 < nb; d2 <<= 1) {  // prefix Hillis-Steele
                    unsigned t0 = tid, t1 = tid + FT;
                    unsigned a0 = (t0 < (unsigned)nb && t0 >= (unsigned)d2) ? bins[t0 - d2] : 0;
                    unsigned a1 = (t1 < (unsigned)nb && t1 >= (unsigned)d2) ? bins[t1 - d2] : 0;
                    __syncthreads();
                    if (t0 < (unsigned)nb) bins[t0] += a0;
                    if (t1 < (unsigned)nb) bins[t1] += a1;
                    __syncthreads();
                }
                for (int t = tid; t < nb; t += FT) {
                    unsigned prev = (t > 0) ? bins[t - 1] : 0;
                    if (bins[t] >= needi && prev < needi) sh_d = (unsigned)t;
                }
                __syncthreads();
                unsigned d2 = sh_d;
                unsigned below = (d2 > 0) ? bins[d2 - 1] : 0;
                __syncthreads();
                needi -= below;
                iprefix |= d2 << sh;
                imask |= ((unsigned)(nb - 1)) << sh;
            }
        }
        if (tid == 0) g_total = 0;
        __syncthreads();
        for (int i = tid; i < n; i += FT) {
            unsigned u = f2u(x[i]);
            bool keep = (u > uTf) || (Rf > 0 && u == uTf && (unsigned)i <= iprefix);
            if (keep) {
                unsigned p = atomicAdd(&g_total, 1u);
                if (p < CAP) g_c64[p] = ((unsigned long long)u << 32)
                                      | (unsigned long long)(unsigned)i;
            }
        }
        __syncthreads();
        T = g_total; if (T > (unsigned)SMEMCAP) T = SMEMCAP;   // == KSEL
        #pragma unroll
        for (int k = 0; k < NPT_CAND; k++) {
            unsigned j = tid + (unsigned)k * FT;
            unsigned long long c = (j < T) ? g_c64[j] : 0ull;
            uk[k] = (unsigned)(c >> 32);
            ui[k] = (unsigned)c;
        }
        uT = 0; cut = 0xffffffffu;       // every staged candidate is a winner
        // re-zero buckets (fallback dirtied them)
        ((uint4*)bcnt)[tid] = make_uint4(0, 0, 0, 0);
        __syncthreads();
    }

    // ---- bucket sort by original index: bucket = idx >> 14 (bcnt pre-zeroed)
    #pragma unroll
    for (int k = 0; k < NPT_CAND; k++) {
        unsigned u = uk[k];
        bool keep = (u > uT) || (u == uT && u != 0u && ui[k] <= cut);
        if (keep) atomicAdd(&bcnt[ui[k] >> 14], 1u);
    }
    __syncthreads();

    excl_scan_nb(bcnt, wsum);

    #pragma unroll
    for (int k = 0; k < NPT_CAND; k++) {
        unsigned u = uk[k];
        bool keep = (u > uT) || (u == uT && u != 0u && ui[k] <= cut);
        if (keep) {
            unsigned r = atomicAdd(&bcnt[ui[k] >> 14], 1u);
            if (r < (unsigned)DST_N)
                dst[r] = ((unsigned long long)ui[k] << 32) | (unsigned long long)u;
        }
    }
    __syncthreads();

    // tiny per-bucket insertion sorts (bucket sizes ~0-9)
    for (unsigned b = tid; b < NB; b += FT) {
        unsigned s0 = (b > 0) ? bcnt[b - 1] : 0;
        unsigned e0 = bcnt[b];
        if (s0 > (unsigned)DST_N) s0 = DST_N;
        if (e0 > (unsigned)DST_N) e0 = DST_N;
        for (unsigned i2 = s0 + 1; i2 < e0; i2++) {
            unsigned long long key = dst[i2];
            unsigned j2 = i2;
            while (j2 > s0 && dst[j2 - 1] > key) { dst[j2] = dst[j2 - 1]; j2--; }
            dst[j2] = key;
        }
    }
    __syncthreads();

    for (unsigned t = tid; t < KSEL; t += FT)
        out[t] = u2f((unsigned)(dst[t] & 0xffffffffu));

    // restore invariants for next graph replay
    ((uint4*)g_hist)[tid] = make_uint4(0, 0, 0, 0);
    if (tid == 0) { g_total = 0; g_ovf = 0; }
}

// ---------------- launch ----------------------------------------------------
extern "C" void kernel_launch(void* const* d_in, const int* in_sizes, int n_in,
                              void* d_out, int out_size) {
    const float* x = (const float*)d_in[0];
    int n = in_sizes[0];
    float* out = (float*)d_out;

    cudaFuncSetAttribute(k_final, cudaFuncAttributeMaxDynamicSharedMemorySize, FIN_SMEM);

    k_compact<<<592, 512>>>(x, n);             // 148 SMs x 4 blocks: one wave

    cudaLaunchConfig_t cfg = {};
    cfg.gridDim = dim3(1, 1, 1);
    cfg.blockDim = dim3(FT, 1, 1);
    cfg.dynamicSmemBytes = FIN_SMEM;
    cudaLaunchAttribute attrs[1];
    attrs[0].id = cudaLaunchAttributeProgrammaticStreamSerialization;
    attrs[0].val.programmaticStreamSerializationAllowed = 1;
    cfg.attrs = attrs;
    cfg.numAttrs = 1;
    cudaLaunchKernelEx(&cfg, k_final, x, n, out);
}